// round 9
// baseline (speedup 1.0000x reference)
#include <cuda_runtime.h>

#define NN 50000
#define EE 800000
#define BB 2
#define NB (NN*BB)
#define SCAN_B 1024
#define NBLK ((NN + SCAN_B - 1) / SCAN_B)   // 49

// -------- scratch (__device__ globals; zero-initialized at module load) ----
__device__ float  g_feat[NN*BB*64];    // [(n*2+b)*64 + h*16+k]
__device__ float  g_el[NN*BB*4];       // [(n*2+b)*4 + h]
__device__ float  g_er[NN*BB*4];
__device__ int    g_deg[NN];           // INVARIANT: zero at entry of each call
__device__ int    g_off[NN + 1];
__device__ int    g_cursor[NN];
__device__ unsigned long long g_tile[NBLK];  // lookback state: zero at entry
__device__ float2 g_edge[EE];          // dst-sorted: (.x = src bits, .y = w)

// ---------------------------------------------------------------------------
// K1: feat = x @ W_fc.T + el/er head dots + degree histogram.
// ---------------------------------------------------------------------------
__global__ void __launch_bounds__(256) k_featcnt(
        const float* __restrict__ x, const float* __restrict__ Wfc,
        const float* __restrict__ al, const float* __restrict__ ar,
        const int* __restrict__ dst) {
    __shared__ float sWT[64 * 68];
    __shared__ float4 sx4[32][16];
    int tid = threadIdx.x;
    int gid = blockIdx.x * 256 + tid;          // in [0, EE) exactly
    atomicAdd(&g_deg[dst[gid]], 1);

    for (int i = tid; i < 4096; i += 256) {    // coalesced W read
        int k = i >> 6, j = i & 63;
        sWT[j * 68 + k] = Wfc[i];
    }
    int k4   = tid & 15;
    int rowh = tid >> 4;
    int r0 = blockIdx.x * 32 + rowh * 2;       // r = b*N + n
    sx4[rowh * 2 + 0][k4] = ((const float4*)x)[(r0 + 0) * 16 + k4];
    sx4[rowh * 2 + 1][k4] = ((const float4*)x)[(r0 + 1) * 16 + k4];
    __syncthreads();

    float4 s0 = make_float4(0.f, 0.f, 0.f, 0.f);
    float4 s1 = make_float4(0.f, 0.f, 0.f, 0.f);
    #pragma unroll
    for (int j4 = 0; j4 < 16; j4++) {
        float4 x0 = sx4[rowh * 2][j4];
        float4 x1 = sx4[rowh * 2 + 1][j4];
        float4 w0 = *(const float4*)&sWT[(4 * j4 + 0) * 68 + 4 * k4];
        float4 w1 = *(const float4*)&sWT[(4 * j4 + 1) * 68 + 4 * k4];
        float4 w2 = *(const float4*)&sWT[(4 * j4 + 2) * 68 + 4 * k4];
        float4 w3 = *(const float4*)&sWT[(4 * j4 + 3) * 68 + 4 * k4];
        s0.x += x0.x*w0.x + x0.y*w1.x + x0.z*w2.x + x0.w*w3.x;
        s0.y += x0.x*w0.y + x0.y*w1.y + x0.z*w2.y + x0.w*w3.y;
        s0.z += x0.x*w0.z + x0.y*w1.z + x0.z*w2.z + x0.w*w3.z;
        s0.w += x0.x*w0.w + x0.y*w1.w + x0.z*w2.w + x0.w*w3.w;
        s1.x += x1.x*w0.x + x1.y*w1.x + x1.z*w2.x + x1.w*w3.x;
        s1.y += x1.x*w0.y + x1.y*w1.y + x1.z*w2.y + x1.w*w3.y;
        s1.z += x1.x*w0.z + x1.y*w1.z + x1.z*w2.z + x1.w*w3.z;
        s1.w += x1.x*w0.w + x1.y*w1.w + x1.z*w2.w + x1.w*w3.w;
    }

    int n0 = r0 % NN, b0 = r0 / NN;
    int r1 = r0 + 1;
    int n1 = r1 % NN, b1 = r1 / NN;
    int gr0 = n0 * 2 + b0, gr1 = n1 * 2 + b1;
    ((float4*)&g_feat[gr0 * 64])[k4] = s0;
    ((float4*)&g_feat[gr1 * 64])[k4] = s1;

    float4 al4 = __ldg(&((const float4*)al)[k4]);
    float4 ar4 = __ldg(&((const float4*)ar)[k4]);
    float pl0 = s0.x*al4.x + s0.y*al4.y + s0.z*al4.z + s0.w*al4.w;
    float pr0 = s0.x*ar4.x + s0.y*ar4.y + s0.z*ar4.z + s0.w*ar4.w;
    float pl1 = s1.x*al4.x + s1.y*al4.y + s1.z*al4.z + s1.w*al4.w;
    float pr1 = s1.x*ar4.x + s1.y*ar4.y + s1.z*ar4.z + s1.w*ar4.w;
    pl0 += __shfl_down_sync(0xffffffffu, pl0, 2);
    pl0 += __shfl_down_sync(0xffffffffu, pl0, 1);
    pr0 += __shfl_down_sync(0xffffffffu, pr0, 2);
    pr0 += __shfl_down_sync(0xffffffffu, pr0, 1);
    pl1 += __shfl_down_sync(0xffffffffu, pl1, 2);
    pl1 += __shfl_down_sync(0xffffffffu, pl1, 1);
    pr1 += __shfl_down_sync(0xffffffffu, pr1, 2);
    pr1 += __shfl_down_sync(0xffffffffu, pr1, 1);
    if ((tid & 3) == 0) {
        int h = k4 >> 2;
        g_el[gr0 * 4 + h] = pl0;  g_er[gr0 * 4 + h] = pr0;
        g_el[gr1 * 4 + h] = pl1;  g_er[gr1 * 4 + h] = pr1;
    }
}

// ---------------------------------------------------------------------------
// K2: single-pass exclusive scan (decoupled lookback, 49 tiles all resident)
// ---------------------------------------------------------------------------
__device__ __forceinline__ int warp_incl_scan(int v, int lane) {
    #pragma unroll
    for (int off = 1; off < 32; off <<= 1) {
        int t = __shfl_up_sync(0xffffffffu, v, off);
        if (lane >= off) v += t;
    }
    return v;
}

__global__ void k_scan() {
    __shared__ int wsum[32];
    __shared__ int s_total;
    __shared__ int s_pref;
    int tid = threadIdx.x, lane = tid & 31, wid = tid >> 5;
    int i = blockIdx.x * SCAN_B + tid;
    int v = (i < NN) ? g_deg[i] : 0;
    int incl = warp_incl_scan(v, lane);
    if (lane == 31) wsum[wid] = incl;
    __syncthreads();
    if (wid == 0) {
        int s = wsum[lane];
        int si = warp_incl_scan(s, lane);
        wsum[lane] = si - s;
        if (lane == 31) s_total = si;
    }
    __syncthreads();
    int excl = incl - v + wsum[wid];
    if (tid == 0) {
        int total = s_total;
        int bx = blockIdx.x;
        if (bx == 0) {
            s_pref = 0;
            *(volatile unsigned long long*)&g_tile[0] =
                (2ULL << 62) | (unsigned int)total;
            g_off[NN] = EE;
        } else {
            *(volatile unsigned long long*)&g_tile[bx] =
                (1ULL << 62) | (unsigned int)total;
            int pref = 0;
            int j = bx - 1;
            while (1) {
                unsigned long long t = *(volatile unsigned long long*)&g_tile[j];
                unsigned int st = (unsigned int)(t >> 62);
                if (st == 0) continue;
                pref += (int)(t & 0xffffffffULL);
                if (st == 2) break;
                j--;
            }
            s_pref = pref;
            *(volatile unsigned long long*)&g_tile[bx] =
                (2ULL << 62) | (unsigned int)(pref + total);
        }
    }
    __syncthreads();
    int off = excl + s_pref;
    if (i < NN) { g_off[i] = off; g_cursor[i] = off; }
}

// ---------------------------------------------------------------------------
// K3: scatter edges into dst-sorted order; also resets g_deg / g_tile for the
// NEXT call (cross-call invariant; cheap kernel absorbs the reset).
// ---------------------------------------------------------------------------
__global__ void k_scatter(const int* __restrict__ src, const int* __restrict__ dst,
                          const float* __restrict__ w) {
    int e = blockIdx.x * blockDim.x + threadIdx.x;
    if (e >= EE) return;
    if (e < NN) g_deg[e] = 0;
    if (e < NBLK) g_tile[e] = 0ULL;
    int t = dst[e];
    int pos = atomicAdd(&g_cursor[t], 1);
    g_edge[pos] = make_float2(__int_as_float(src[e]), w[e]);
}

// ---------------------------------------------------------------------------
// K4: one warp per node. Lane owns float4 j=4*lane of the 128-wide (b,h,k)
// vector => one (b,h) exp per lane per edge, one LDG.128 feat. Unroll x4
// (4 independent gather chains). No max tracking (shift-invariant softmax).
// ---------------------------------------------------------------------------
__device__ __forceinline__ float lk(float v) { return (v > 0.f) ? v : 0.1f * v; }

__global__ void __launch_bounds__(256) k_agg_out(
        const float* __restrict__ Wout, const float* __restrict__ bout,
        float* __restrict__ out) {
    __shared__ float sAcc[8][128];
    int tid = threadIdx.x;
    int warp = tid >> 5;
    int lane = tid & 31;
    int n = blockIdx.x * 8 + warp;
    if (n >= NN) return;

    int q = lane >> 2;                  // (b*4 + h) for this lane
    float er_l = g_er[n * 8 + q];

    int beg = g_off[n], end = g_off[n + 1];

    float4 a = make_float4(0.f, 0.f, 0.f, 0.f);
    float  d = 0.f;

    int e = beg;
    if ((e & 1) && e < end) {            // head peel -> e even (16B alignment)
        float2 ed = __ldg(&g_edge[e]);
        int   s  = __float_as_int(ed.x);
        float xs = __expf(lk(__ldg(&g_el[s * 8 + q]) + er_l) * ed.y);
        float4 f = __ldg((const float4*)&g_feat[s * 128 + 4 * lane]);
        d += xs;
        a.x += xs * f.x; a.y += xs * f.y; a.z += xs * f.z; a.w += xs * f.w;
        e++;
    }
    for (; e + 3 < end; e += 4) {        // 4 independent chains, aligned loads
        float4 eAB = __ldg((const float4*)&g_edge[e]);
        float4 eCD = __ldg((const float4*)&g_edge[e + 2]);
        int sA = __float_as_int(eAB.x), sB = __float_as_int(eAB.z);
        int sC = __float_as_int(eCD.x), sD = __float_as_int(eCD.z);

        float elA = __ldg(&g_el[sA * 8 + q]);
        float elB = __ldg(&g_el[sB * 8 + q]);
        float elC = __ldg(&g_el[sC * 8 + q]);
        float elD = __ldg(&g_el[sD * 8 + q]);
        float4 fA = __ldg((const float4*)&g_feat[sA * 128 + 4 * lane]);
        float4 fB = __ldg((const float4*)&g_feat[sB * 128 + 4 * lane]);
        float4 fC = __ldg((const float4*)&g_feat[sC * 128 + 4 * lane]);
        float4 fD = __ldg((const float4*)&g_feat[sD * 128 + 4 * lane]);

        float xA = __expf(lk(elA + er_l) * eAB.y);
        float xB = __expf(lk(elB + er_l) * eAB.w);
        float xC = __expf(lk(elC + er_l) * eCD.y);
        float xD = __expf(lk(elD + er_l) * eCD.w);
        d += (xA + xB) + (xC + xD);
        a.x += xA * fA.x + xB * fB.x + xC * fC.x + xD * fD.x;
        a.y += xA * fA.y + xB * fB.y + xC * fC.y + xD * fD.y;
        a.z += xA * fA.z + xB * fB.z + xC * fC.z + xD * fD.z;
        a.w += xA * fA.w + xB * fB.w + xC * fC.w + xD * fD.w;
    }
    for (; e < end; e++) {               // tail (0..3)
        float2 ed = __ldg(&g_edge[e]);
        int   s  = __float_as_int(ed.x);
        float xs = __expf(lk(__ldg(&g_el[s * 8 + q]) + er_l) * ed.y);
        float4 f = __ldg((const float4*)&g_feat[s * 128 + 4 * lane]);
        d += xs;
        a.x += xs * f.x; a.y += xs * f.y; a.z += xs * f.z; a.w += xs * f.w;
    }

    float inv = (d > 0.f) ? 1.f / d : 0.f;
    *(float4*)&sAcc[warp][4 * lane] =
        make_float4(a.x * inv, a.y * inv, a.z * inv, a.w * inv);
    __syncwarp();

    float4 wA[4], wB[4];
    #pragma unroll
    for (int qq = 0; qq < 4; qq++) {
        wA[qq] = __ldg(&((const float4*)&Wout[lane * 16])[qq]);
        wB[qq] = __ldg(&((const float4*)&Wout[(lane + 32) * 16])[qq]);
    }
    float bias0 = __ldg(&bout[lane]), bias1 = __ldg(&bout[lane + 32]);

    #pragma unroll
    for (int b = 0; b < 2; b++) {
        #pragma unroll
        for (int h = 0; h < 4; h++) {
            const float4* ap = (const float4*)&sAcc[warp][b * 64 + h * 16];
            float acc0 = bias0, acc1 = bias1;
            #pragma unroll
            for (int qq = 0; qq < 4; qq++) {
                float4 av = ap[qq];
                acc0 += av.x * wA[qq].x + av.y * wA[qq].y + av.z * wA[qq].z + av.w * wA[qq].w;
                acc1 += av.x * wB[qq].x + av.y * wB[qq].y + av.z * wB[qq].z + av.w * wB[qq].w;
            }
            float* op = &out[((b * NN + n) * 4 + h) * 64];
            op[lane]      = acc0;
            op[lane + 32] = acc1;
        }
    }
}

// ---------------------------------------------------------------------------
// inputs: vt, x, w, src, dst, W_fc, attn_l, attn_r, W_out, b_out
// ---------------------------------------------------------------------------
extern "C" void kernel_launch(void* const* d_in, const int* in_sizes, int n_in,
                              void* d_out, int out_size) {
    const float* x    = (const float*)d_in[1];
    const float* w    = (const float*)d_in[2];
    const int*   src  = (const int*)  d_in[3];
    const int*   dst  = (const int*)  d_in[4];
    const float* Wfc  = (const float*)d_in[5];
    const float* al   = (const float*)d_in[6];
    const float* ar   = (const float*)d_in[7];
    const float* Wout = (const float*)d_in[8];
    const float* bout = (const float*)d_in[9];
    float* out = (float*)d_out;

    k_featcnt<<<NB / 32, 256>>>(x, Wfc, al, ar, dst);   // 3125 blocks
    k_scan<<<NBLK, SCAN_B>>>();
    k_scatter<<<(EE + 255) / 256, 256>>>(src, dst, w);
    k_agg_out<<<(NN + 7) / 8, 256>>>(Wout, bout, out);
}

// round 12
// speedup vs baseline: 1.0466x; 1.0466x over previous
#include <cuda_runtime.h>
#include <cuda_fp16.h>

#define NN 50000
#define EE 800000
#define BB 2
#define NB (NN*BB)
#define SCAN_B 1024
#define NBLK ((NN + SCAN_B - 1) / SCAN_B)   // 49

// -------- scratch (__device__ globals; zero-initialized at module load) ----
__device__ __half g_feat[NN*BB*64];    // fp16 storage: [(n*2+b)*64 + h*16+k]
__device__ float  g_el[NN*BB*4];       // [(n*2+b)*4 + h]
__device__ float  g_er[NN*BB*4];
__device__ int    g_deg[NN];           // INVARIANT: zero at entry of each call
__device__ int    g_off[NN + 1];
__device__ int    g_cursor[NN];
__device__ unsigned long long g_tile[NBLK];  // lookback state: zero at entry
__device__ float2 g_edge[EE];          // dst-sorted: (.x = src bits, .y = w)

__device__ __forceinline__ unsigned int h2_bits(__half2 h) {
    return *reinterpret_cast<unsigned int*>(&h);
}
__device__ __forceinline__ __half2 bits_h2(unsigned int u) {
    return *reinterpret_cast<__half2*>(&u);
}

// ---------------------------------------------------------------------------
// K1: feat = x @ W_fc.T + el/er head dots + degree histogram. feat -> fp16.
// ---------------------------------------------------------------------------
__global__ void __launch_bounds__(256) k_featcnt(
        const float* __restrict__ x, const float* __restrict__ Wfc,
        const float* __restrict__ al, const float* __restrict__ ar,
        const int* __restrict__ dst) {
    __shared__ float sWT[64 * 68];
    __shared__ float4 sx4[32][16];
    int tid = threadIdx.x;
    int gid = blockIdx.x * 256 + tid;          // in [0, EE) exactly
    atomicAdd(&g_deg[dst[gid]], 1);

    for (int i = tid; i < 4096; i += 256) {    // coalesced W read
        int k = i >> 6, j = i & 63;
        sWT[j * 68 + k] = Wfc[i];
    }
    int k4   = tid & 15;
    int rowh = tid >> 4;
    int r0 = blockIdx.x * 32 + rowh * 2;       // r = b*N + n
    sx4[rowh * 2 + 0][k4] = ((const float4*)x)[(r0 + 0) * 16 + k4];
    sx4[rowh * 2 + 1][k4] = ((const float4*)x)[(r0 + 1) * 16 + k4];
    __syncthreads();

    float4 s0 = make_float4(0.f, 0.f, 0.f, 0.f);
    float4 s1 = make_float4(0.f, 0.f, 0.f, 0.f);
    #pragma unroll
    for (int j4 = 0; j4 < 16; j4++) {
        float4 x0 = sx4[rowh * 2][j4];
        float4 x1 = sx4[rowh * 2 + 1][j4];
        float4 w0 = *(const float4*)&sWT[(4 * j4 + 0) * 68 + 4 * k4];
        float4 w1 = *(const float4*)&sWT[(4 * j4 + 1) * 68 + 4 * k4];
        float4 w2 = *(const float4*)&sWT[(4 * j4 + 2) * 68 + 4 * k4];
        float4 w3 = *(const float4*)&sWT[(4 * j4 + 3) * 68 + 4 * k4];
        s0.x += x0.x*w0.x + x0.y*w1.x + x0.z*w2.x + x0.w*w3.x;
        s0.y += x0.x*w0.y + x0.y*w1.y + x0.z*w2.y + x0.w*w3.y;
        s0.z += x0.x*w0.z + x0.y*w1.z + x0.z*w2.z + x0.w*w3.z;
        s0.w += x0.x*w0.w + x0.y*w1.w + x0.z*w2.w + x0.w*w3.w;
        s1.x += x1.x*w0.x + x1.y*w1.x + x1.z*w2.x + x1.w*w3.x;
        s1.y += x1.x*w0.y + x1.y*w1.y + x1.z*w2.y + x1.w*w3.y;
        s1.z += x1.x*w0.z + x1.y*w1.z + x1.z*w2.z + x1.w*w3.z;
        s1.w += x1.x*w0.w + x1.y*w1.w + x1.z*w2.w + x1.w*w3.w;
    }

    int n0 = r0 % NN, b0 = r0 / NN;
    int r1 = r0 + 1;
    int n1 = r1 % NN, b1 = r1 / NN;
    int gr0 = n0 * 2 + b0, gr1 = n1 * 2 + b1;
    {   // fp16 pack: 4 floats -> 2 half2 -> uint2 store (8B aligned)
        uint2 u0, u1;
        u0.x = h2_bits(__float22half2_rn(make_float2(s0.x, s0.y)));
        u0.y = h2_bits(__float22half2_rn(make_float2(s0.z, s0.w)));
        u1.x = h2_bits(__float22half2_rn(make_float2(s1.x, s1.y)));
        u1.y = h2_bits(__float22half2_rn(make_float2(s1.z, s1.w)));
        ((uint2*)&g_feat[gr0 * 64])[k4] = u0;
        ((uint2*)&g_feat[gr1 * 64])[k4] = u1;
    }

    float4 al4 = __ldg(&((const float4*)al)[k4]);
    float4 ar4 = __ldg(&((const float4*)ar)[k4]);
    float pl0 = s0.x*al4.x + s0.y*al4.y + s0.z*al4.z + s0.w*al4.w;
    float pr0 = s0.x*ar4.x + s0.y*ar4.y + s0.z*ar4.z + s0.w*ar4.w;
    float pl1 = s1.x*al4.x + s1.y*al4.y + s1.z*al4.z + s1.w*al4.w;
    float pr1 = s1.x*ar4.x + s1.y*ar4.y + s1.z*ar4.z + s1.w*ar4.w;
    pl0 += __shfl_down_sync(0xffffffffu, pl0, 2);
    pl0 += __shfl_down_sync(0xffffffffu, pl0, 1);
    pr0 += __shfl_down_sync(0xffffffffu, pr0, 2);
    pr0 += __shfl_down_sync(0xffffffffu, pr0, 1);
    pl1 += __shfl_down_sync(0xffffffffu, pl1, 2);
    pl1 += __shfl_down_sync(0xffffffffu, pl1, 1);
    pr1 += __shfl_down_sync(0xffffffffu, pr1, 2);
    pr1 += __shfl_down_sync(0xffffffffu, pr1, 1);
    if ((tid & 3) == 0) {
        int h = k4 >> 2;
        g_el[gr0 * 4 + h] = pl0;  g_er[gr0 * 4 + h] = pr0;
        g_el[gr1 * 4 + h] = pl1;  g_er[gr1 * 4 + h] = pr1;
    }
}

// ---------------------------------------------------------------------------
// K2: single-pass exclusive scan (decoupled lookback, 49 tiles all resident)
// ---------------------------------------------------------------------------
__device__ __forceinline__ int warp_incl_scan(int v, int lane) {
    #pragma unroll
    for (int off = 1; off < 32; off <<= 1) {
        int t = __shfl_up_sync(0xffffffffu, v, off);
        if (lane >= off) v += t;
    }
    return v;
}

__global__ void k_scan() {
    __shared__ int wsum[32];
    __shared__ int s_total;
    __shared__ int s_pref;
    int tid = threadIdx.x, lane = tid & 31, wid = tid >> 5;
    int i = blockIdx.x * SCAN_B + tid;
    int v = (i < NN) ? g_deg[i] : 0;
    int incl = warp_incl_scan(v, lane);
    if (lane == 31) wsum[wid] = incl;
    __syncthreads();
    if (wid == 0) {
        int s = wsum[lane];
        int si = warp_incl_scan(s, lane);
        wsum[lane] = si - s;
        if (lane == 31) s_total = si;
    }
    __syncthreads();
    int excl = incl - v + wsum[wid];
    if (tid == 0) {
        int total = s_total;
        int bx = blockIdx.x;
        if (bx == 0) {
            s_pref = 0;
            *(volatile unsigned long long*)&g_tile[0] =
                (2ULL << 62) | (unsigned int)total;
            g_off[NN] = EE;
        } else {
            *(volatile unsigned long long*)&g_tile[bx] =
                (1ULL << 62) | (unsigned int)total;
            int pref = 0;
            int j = bx - 1;
            while (1) {
                unsigned long long t = *(volatile unsigned long long*)&g_tile[j];
                unsigned int st = (unsigned int)(t >> 62);
                if (st == 0) continue;
                pref += (int)(t & 0xffffffffULL);
                if (st == 2) break;
                j--;
            }
            s_pref = pref;
            *(volatile unsigned long long*)&g_tile[bx] =
                (2ULL << 62) | (unsigned int)(pref + total);
        }
    }
    __syncthreads();
    int off = excl + s_pref;
    if (i < NN) { g_off[i] = off; g_cursor[i] = off; }
}

// ---------------------------------------------------------------------------
// K3: scatter edges into dst-sorted order; resets g_deg / g_tile for the
// NEXT call (cross-call invariant).
// ---------------------------------------------------------------------------
__global__ void k_scatter(const int* __restrict__ src, const int* __restrict__ dst,
                          const float* __restrict__ w) {
    int e = blockIdx.x * blockDim.x + threadIdx.x;
    if (e >= EE) return;
    if (e < NN) g_deg[e] = 0;
    if (e < NBLK) g_tile[e] = 0ULL;
    int t = dst[e];
    int pos = atomicAdd(&g_cursor[t], 1);
    g_edge[pos] = make_float2(__int_as_float(src[e]), w[e]);
}

// ---------------------------------------------------------------------------
// K4: one warp per node. Lane owns 4 elems (one (b,h)); feat gather is one
// 8B fp16 load per lane per edge. No max tracking. Unroll x2.
// ---------------------------------------------------------------------------
__device__ __forceinline__ float lk(float v) { return (v > 0.f) ? v : 0.1f * v; }

__device__ __forceinline__ void feat4(int s, int lane, float2& f01, float2& f23) {
    uint2 u = __ldg((const uint2*)(g_feat + s * 128 + 4 * lane));
    f01 = __half22float2(bits_h2(u.x));
    f23 = __half22float2(bits_h2(u.y));
}

__global__ void __launch_bounds__(256) k_agg_out(
        const float* __restrict__ Wout, const float* __restrict__ bout,
        float* __restrict__ out) {
    __shared__ float sAcc[8][128];
    int tid = threadIdx.x;
    int warp = tid >> 5;
    int lane = tid & 31;
    int n = blockIdx.x * 8 + warp;
    if (n >= NN) return;

    int q = lane >> 2;                  // (b*4 + h) for this lane
    float er_l = g_er[n * 8 + q];

    int beg = g_off[n], end = g_off[n + 1];

    float4 a = make_float4(0.f, 0.f, 0.f, 0.f);
    float  d = 0.f;

    int e = beg;
    if ((e & 1) && e < end) {            // head peel -> e even (16B alignment)
        float2 ed = __ldg(&g_edge[e]);
        int   s  = __float_as_int(ed.x);
        float xs = __expf(lk(__ldg(&g_el[s * 8 + q]) + er_l) * ed.y);
        float2 f01, f23; feat4(s, lane, f01, f23);
        d += xs;
        a.x += xs * f01.x; a.y += xs * f01.y; a.z += xs * f23.x; a.w += xs * f23.y;
        e++;
    }
    for (; e + 1 < end; e += 2) {        // e even: aligned float4 edge load
        float4 eAB = __ldg((const float4*)&g_edge[e]);
        int sA = __float_as_int(eAB.x), sB = __float_as_int(eAB.z);

        float elA = __ldg(&g_el[sA * 8 + q]);
        float elB = __ldg(&g_el[sB * 8 + q]);
        float2 fA01, fA23; feat4(sA, lane, fA01, fA23);
        float2 fB01, fB23; feat4(sB, lane, fB01, fB23);

        float xA = __expf(lk(elA + er_l) * eAB.y);
        float xB = __expf(lk(elB + er_l) * eAB.w);
        d += xA + xB;
        a.x += xA * fA01.x + xB * fB01.x;
        a.y += xA * fA01.y + xB * fB01.y;
        a.z += xA * fA23.x + xB * fB23.x;
        a.w += xA * fA23.y + xB * fB23.y;
    }
    if (e < end) {                       // tail edge
        float2 ed = __ldg(&g_edge[e]);
        int   s  = __float_as_int(ed.x);
        float xs = __expf(lk(__ldg(&g_el[s * 8 + q]) + er_l) * ed.y);
        float2 f01, f23; feat4(s, lane, f01, f23);
        d += xs;
        a.x += xs * f01.x; a.y += xs * f01.y; a.z += xs * f23.x; a.w += xs * f23.y;
    }

    float inv = (d > 0.f) ? 1.f / d : 0.f;
    *(float4*)&sAcc[warp][4 * lane] =
        make_float4(a.x * inv, a.y * inv, a.z * inv, a.w * inv);
    __syncwarp();

    float4 wA[4], wB[4];
    #pragma unroll
    for (int qq = 0; qq < 4; qq++) {
        wA[qq] = __ldg(&((const float4*)&Wout[lane * 16])[qq]);
        wB[qq] = __ldg(&((const float4*)&Wout[(lane + 32) * 16])[qq]);
    }
    float bias0 = __ldg(&bout[lane]), bias1 = __ldg(&bout[lane + 32]);

    #pragma unroll
    for (int b = 0; b < 2; b++) {
        #pragma unroll
        for (int h = 0; h < 4; h++) {
            const float4* ap = (const float4*)&sAcc[warp][b * 64 + h * 16];
            float acc0 = bias0, acc1 = bias1;
            #pragma unroll
            for (int qq = 0; qq < 4; qq++) {
                float4 av = ap[qq];
                acc0 += av.x * wA[qq].x + av.y * wA[qq].y + av.z * wA[qq].z + av.w * wA[qq].w;
                acc1 += av.x * wB[qq].x + av.y * wB[qq].y + av.z * wB[qq].z + av.w * wB[qq].w;
            }
            float* op = &out[((b * NN + n) * 4 + h) * 64];
            op[lane]      = acc0;
            op[lane + 32] = acc1;
        }
    }
}

// ---------------------------------------------------------------------------
// inputs: vt, x, w, src, dst, W_fc, attn_l, attn_r, W_out, b_out
// ---------------------------------------------------------------------------
extern "C" void kernel_launch(void* const* d_in, const int* in_sizes, int n_in,
                              void* d_out, int out_size) {
    const float* x    = (const float*)d_in[1];
    const float* w    = (const float*)d_in[2];
    const int*   src  = (const int*)  d_in[3];
    const int*   dst  = (const int*)  d_in[4];
    const float* Wfc  = (const float*)d_in[5];
    const float* al   = (const float*)d_in[6];
    const float* ar   = (const float*)d_in[7];
    const float* Wout = (const float*)d_in[8];
    const float* bout = (const float*)d_in[9];
    float* out = (float*)d_out;

    k_featcnt<<<NB / 32, 256>>>(x, Wfc, al, ar, dst);   // 3125 blocks
    k_scan<<<NBLK, SCAN_B>>>();
    k_scatter<<<(EE + 255) / 256, 256>>>(src, dst, w);
    k_agg_out<<<(NN + 7) / 8, 256>>>(Wout, bout, out);
}

// round 13
// speedup vs baseline: 1.0873x; 1.0389x over previous
#include <cuda_runtime.h>
#include <cuda_fp16.h>

#define NN 50000
#define EE 800000
#define BB 2
#define NB (NN*BB)
#define SCAN_B 1024
#define NBLK ((NN + SCAN_B - 1) / SCAN_B)   // 49

// -------- scratch (__device__ globals; zero-initialized at module load) ----
__device__ __half g_feat[NN*BB*64];    // fp16 storage: [(n*2+b)*64 + h*16+k]
__device__ float  g_el[NN*BB*4];       // [(n*2+b)*4 + h]
__device__ float  g_er[NN*BB*4];
__device__ int    g_deg[NN];           // INVARIANT: zero at entry of each call
__device__ int    g_off[NN + 1];
__device__ int    g_cursor[NN];
__device__ unsigned long long g_tile[NBLK];  // lookback state: zero at entry
__device__ float2 g_edge[EE];          // dst-sorted: (.x = src bits, .y = w)

__device__ __forceinline__ unsigned int h2_bits(__half2 h) {
    return *reinterpret_cast<unsigned int*>(&h);
}
__device__ __forceinline__ __half2 bits_h2(unsigned int u) {
    return *reinterpret_cast<__half2*>(&u);
}

// ---------------------------------------------------------------------------
// K1: feat = x @ W_fc.T + el/er head dots + degree histogram. feat -> fp16.
// ---------------------------------------------------------------------------
__global__ void __launch_bounds__(256) k_featcnt(
        const float* __restrict__ x, const float* __restrict__ Wfc,
        const float* __restrict__ al, const float* __restrict__ ar,
        const int* __restrict__ dst) {
    __shared__ float sWT[64 * 68];
    __shared__ float4 sx4[32][16];
    int tid = threadIdx.x;
    int gid = blockIdx.x * 256 + tid;          // in [0, EE) exactly
    atomicAdd(&g_deg[dst[gid]], 1);

    for (int i = tid; i < 4096; i += 256) {    // coalesced W read
        int k = i >> 6, j = i & 63;
        sWT[j * 68 + k] = Wfc[i];
    }
    int k4   = tid & 15;
    int rowh = tid >> 4;
    int r0 = blockIdx.x * 32 + rowh * 2;       // r = b*N + n
    sx4[rowh * 2 + 0][k4] = ((const float4*)x)[(r0 + 0) * 16 + k4];
    sx4[rowh * 2 + 1][k4] = ((const float4*)x)[(r0 + 1) * 16 + k4];
    __syncthreads();

    float4 s0 = make_float4(0.f, 0.f, 0.f, 0.f);
    float4 s1 = make_float4(0.f, 0.f, 0.f, 0.f);
    #pragma unroll
    for (int j4 = 0; j4 < 16; j4++) {
        float4 x0 = sx4[rowh * 2][j4];
        float4 x1 = sx4[rowh * 2 + 1][j4];
        float4 w0 = *(const float4*)&sWT[(4 * j4 + 0) * 68 + 4 * k4];
        float4 w1 = *(const float4*)&sWT[(4 * j4 + 1) * 68 + 4 * k4];
        float4 w2 = *(const float4*)&sWT[(4 * j4 + 2) * 68 + 4 * k4];
        float4 w3 = *(const float4*)&sWT[(4 * j4 + 3) * 68 + 4 * k4];
        s0.x += x0.x*w0.x + x0.y*w1.x + x0.z*w2.x + x0.w*w3.x;
        s0.y += x0.x*w0.y + x0.y*w1.y + x0.z*w2.y + x0.w*w3.y;
        s0.z += x0.x*w0.z + x0.y*w1.z + x0.z*w2.z + x0.w*w3.z;
        s0.w += x0.x*w0.w + x0.y*w1.w + x0.z*w2.w + x0.w*w3.w;
        s1.x += x1.x*w0.x + x1.y*w1.x + x1.z*w2.x + x1.w*w3.x;
        s1.y += x1.x*w0.y + x1.y*w1.y + x1.z*w2.y + x1.w*w3.y;
        s1.z += x1.x*w0.z + x1.y*w1.z + x1.z*w2.z + x1.w*w3.z;
        s1.w += x1.x*w0.w + x1.y*w1.w + x1.z*w2.w + x1.w*w3.w;
    }

    int n0 = r0 % NN, b0 = r0 / NN;
    int r1 = r0 + 1;
    int n1 = r1 % NN, b1 = r1 / NN;
    int gr0 = n0 * 2 + b0, gr1 = n1 * 2 + b1;
    {   // fp16 pack: 4 floats -> 2 half2 -> uint2 store (8B aligned)
        uint2 u0, u1;
        u0.x = h2_bits(__float22half2_rn(make_float2(s0.x, s0.y)));
        u0.y = h2_bits(__float22half2_rn(make_float2(s0.z, s0.w)));
        u1.x = h2_bits(__float22half2_rn(make_float2(s1.x, s1.y)));
        u1.y = h2_bits(__float22half2_rn(make_float2(s1.z, s1.w)));
        ((uint2*)&g_feat[gr0 * 64])[k4] = u0;
        ((uint2*)&g_feat[gr1 * 64])[k4] = u1;
    }

    float4 al4 = __ldg(&((const float4*)al)[k4]);
    float4 ar4 = __ldg(&((const float4*)ar)[k4]);
    float pl0 = s0.x*al4.x + s0.y*al4.y + s0.z*al4.z + s0.w*al4.w;
    float pr0 = s0.x*ar4.x + s0.y*ar4.y + s0.z*ar4.z + s0.w*ar4.w;
    float pl1 = s1.x*al4.x + s1.y*al4.y + s1.z*al4.z + s1.w*al4.w;
    float pr1 = s1.x*ar4.x + s1.y*ar4.y + s1.z*ar4.z + s1.w*ar4.w;
    pl0 += __shfl_down_sync(0xffffffffu, pl0, 2);
    pl0 += __shfl_down_sync(0xffffffffu, pl0, 1);
    pr0 += __shfl_down_sync(0xffffffffu, pr0, 2);
    pr0 += __shfl_down_sync(0xffffffffu, pr0, 1);
    pl1 += __shfl_down_sync(0xffffffffu, pl1, 2);
    pl1 += __shfl_down_sync(0xffffffffu, pl1, 1);
    pr1 += __shfl_down_sync(0xffffffffu, pr1, 2);
    pr1 += __shfl_down_sync(0xffffffffu, pr1, 1);
    if ((tid & 3) == 0) {
        int h = k4 >> 2;
        g_el[gr0 * 4 + h] = pl0;  g_er[gr0 * 4 + h] = pr0;
        g_el[gr1 * 4 + h] = pl1;  g_er[gr1 * 4 + h] = pr1;
    }
}

// ---------------------------------------------------------------------------
// K2: single-pass exclusive scan (decoupled lookback, 49 tiles all resident)
// ---------------------------------------------------------------------------
__device__ __forceinline__ int warp_incl_scan(int v, int lane) {
    #pragma unroll
    for (int off = 1; off < 32; off <<= 1) {
        int t = __shfl_up_sync(0xffffffffu, v, off);
        if (lane >= off) v += t;
    }
    return v;
}

__global__ void k_scan() {
    __shared__ int wsum[32];
    __shared__ int s_total;
    __shared__ int s_pref;
    int tid = threadIdx.x, lane = tid & 31, wid = tid >> 5;
    int i = blockIdx.x * SCAN_B + tid;
    int v = (i < NN) ? g_deg[i] : 0;
    int incl = warp_incl_scan(v, lane);
    if (lane == 31) wsum[wid] = incl;
    __syncthreads();
    if (wid == 0) {
        int s = wsum[lane];
        int si = warp_incl_scan(s, lane);
        wsum[lane] = si - s;
        if (lane == 31) s_total = si;
    }
    __syncthreads();
    int excl = incl - v + wsum[wid];
    if (tid == 0) {
        int total = s_total;
        int bx = blockIdx.x;
        if (bx == 0) {
            s_pref = 0;
            *(volatile unsigned long long*)&g_tile[0] =
                (2ULL << 62) | (unsigned int)total;
            g_off[NN] = EE;
        } else {
            *(volatile unsigned long long*)&g_tile[bx] =
                (1ULL << 62) | (unsigned int)total;
            int pref = 0;
            int j = bx - 1;
            while (1) {
                unsigned long long t = *(volatile unsigned long long*)&g_tile[j];
                unsigned int st = (unsigned int)(t >> 62);
                if (st == 0) continue;
                pref += (int)(t & 0xffffffffULL);
                if (st == 2) break;
                j--;
            }
            s_pref = pref;
            *(volatile unsigned long long*)&g_tile[bx] =
                (2ULL << 62) | (unsigned int)(pref + total);
        }
    }
    __syncthreads();
    int off = excl + s_pref;
    if (i < NN) { g_off[i] = off; g_cursor[i] = off; }
}

// ---------------------------------------------------------------------------
// K3: scatter edges into dst-sorted order; resets g_deg / g_tile for the
// NEXT call (cross-call invariant).
// ---------------------------------------------------------------------------
__global__ void k_scatter(const int* __restrict__ src, const int* __restrict__ dst,
                          const float* __restrict__ w) {
    int e = blockIdx.x * blockDim.x + threadIdx.x;
    if (e >= EE) return;
    if (e < NN) g_deg[e] = 0;
    if (e < NBLK) g_tile[e] = 0ULL;
    int t = dst[e];
    int pos = atomicAdd(&g_cursor[t], 1);
    g_edge[pos] = make_float2(__int_as_float(src[e]), w[e]);
}

// ---------------------------------------------------------------------------
// K4: one warp per node. Lane owns 4 elems (one (b,h)); feat gather is one
// 8B fp16 load per lane per edge. No max tracking. Unroll x2.
// Two-pass epilogue (reuse w registers) + forced 6 blocks/SM for occupancy.
// ---------------------------------------------------------------------------
__device__ __forceinline__ float lk(float v) { return (v > 0.f) ? v : 0.1f * v; }

__device__ __forceinline__ void feat4(int s, int lane, float2& f01, float2& f23) {
    uint2 u = __ldg((const uint2*)(g_feat + s * 128 + 4 * lane));
    f01 = __half22float2(bits_h2(u.x));
    f23 = __half22float2(bits_h2(u.y));
}

__global__ void __launch_bounds__(256, 6) k_agg_out(
        const float* __restrict__ Wout, const float* __restrict__ bout,
        float* __restrict__ out) {
    __shared__ float sAcc[8][128];
    int tid = threadIdx.x;
    int warp = tid >> 5;
    int lane = tid & 31;
    int n = blockIdx.x * 8 + warp;
    if (n >= NN) return;

    int q = lane >> 2;                  // (b*4 + h) for this lane
    float er_l = g_er[n * 8 + q];

    int beg = g_off[n], end = g_off[n + 1];

    float4 a = make_float4(0.f, 0.f, 0.f, 0.f);
    float  d = 0.f;

    int e = beg;
    if ((e & 1) && e < end) {            // head peel -> e even (16B alignment)
        float2 ed = __ldg(&g_edge[e]);
        int   s  = __float_as_int(ed.x);
        float xs = __expf(lk(__ldg(&g_el[s * 8 + q]) + er_l) * ed.y);
        float2 f01, f23; feat4(s, lane, f01, f23);
        d += xs;
        a.x += xs * f01.x; a.y += xs * f01.y; a.z += xs * f23.x; a.w += xs * f23.y;
        e++;
    }
    for (; e + 1 < end; e += 2) {        // e even: aligned float4 edge load
        float4 eAB = __ldg((const float4*)&g_edge[e]);
        int sA = __float_as_int(eAB.x), sB = __float_as_int(eAB.z);

        float elA = __ldg(&g_el[sA * 8 + q]);
        float elB = __ldg(&g_el[sB * 8 + q]);
        float2 fA01, fA23; feat4(sA, lane, fA01, fA23);
        float2 fB01, fB23; feat4(sB, lane, fB01, fB23);

        float xA = __expf(lk(elA + er_l) * eAB.y);
        float xB = __expf(lk(elB + er_l) * eAB.w);
        d += xA + xB;
        a.x += xA * fA01.x + xB * fB01.x;
        a.y += xA * fA01.y + xB * fB01.y;
        a.z += xA * fA23.x + xB * fB23.x;
        a.w += xA * fA23.y + xB * fB23.y;
    }
    if (e < end) {                       // tail edge
        float2 ed = __ldg(&g_edge[e]);
        int   s  = __float_as_int(ed.x);
        float xs = __expf(lk(__ldg(&g_el[s * 8 + q]) + er_l) * ed.y);
        float2 f01, f23; feat4(s, lane, f01, f23);
        d += xs;
        a.x += xs * f01.x; a.y += xs * f01.y; a.z += xs * f23.x; a.w += xs * f23.y;
    }

    float inv = (d > 0.f) ? 1.f / d : 0.f;
    *(float4*)&sAcc[warp][4 * lane] =
        make_float4(a.x * inv, a.y * inv, a.z * inv, a.w * inv);
    __syncwarp();

    // ---- two-pass epilogue: pass 0 -> columns [0,32) with w rows `lane`,
    //      pass 1 -> columns [32,64) with w rows `lane+32` (registers reused)
    #pragma unroll
    for (int pass = 0; pass < 2; pass++) {
        int o = lane + pass * 32;
        float4 wR[4];
        #pragma unroll
        for (int qq = 0; qq < 4; qq++)
            wR[qq] = __ldg(&((const float4*)&Wout[o * 16])[qq]);
        float bias = __ldg(&bout[o]);

        #pragma unroll
        for (int b = 0; b < 2; b++) {
            #pragma unroll
            for (int h = 0; h < 4; h++) {
                const float4* ap = (const float4*)&sAcc[warp][b * 64 + h * 16];
                float acc = bias;
                #pragma unroll
                for (int qq = 0; qq < 4; qq++) {
                    float4 av = ap[qq];
                    acc += av.x * wR[qq].x + av.y * wR[qq].y
                         + av.z * wR[qq].z + av.w * wR[qq].w;
                }
                out[((b * NN + n) * 4 + h) * 64 + o] = acc;
            }
        }
    }
}

// ---------------------------------------------------------------------------
// inputs: vt, x, w, src, dst, W_fc, attn_l, attn_r, W_out, b_out
// ---------------------------------------------------------------------------
extern "C" void kernel_launch(void* const* d_in, const int* in_sizes, int n_in,
                              void* d_out, int out_size) {
    const float* x    = (const float*)d_in[1];
    const float* w    = (const float*)d_in[2];
    const int*   src  = (const int*)  d_in[3];
    const int*   dst  = (const int*)  d_in[4];
    const float* Wfc  = (const float*)d_in[5];
    const float* al   = (const float*)d_in[6];
    const float* ar   = (const float*)d_in[7];
    const float* Wout = (const float*)d_in[8];
    const float* bout = (const float*)d_in[9];
    float* out = (float*)d_out;

    k_featcnt<<<NB / 32, 256>>>(x, Wfc, al, ar, dst);   // 3125 blocks
    k_scan<<<NBLK, SCAN_B>>>();
    k_scatter<<<(EE + 255) / 256, 256>>>(src, dst, w);
    k_agg_out<<<(NN + 7) / 8, 256>>>(Wout, bout, out);
}

// round 14
// speedup vs baseline: 1.1411x; 1.0495x over previous
#include <cuda_runtime.h>
#include <cuda_fp16.h>

#define NN 50000
#define EE 800000
#define BB 2
#define NB (NN*BB)
#define SCAN_B 1024
#define NBLK ((NN + SCAN_B - 1) / SCAN_B)   // 49
#define FC_BLOCKS ((NB + 63) / 64)           // 1563, 64 rows per block
#define FC_THREADS (FC_BLOCKS * 256)         // 400128

// -------- scratch (__device__ globals; zero-initialized at module load) ----
__device__ __half g_feat[NN*BB*64];    // fp16 storage: [(n*2+b)*64 + h*16+k]
__device__ float  g_el[NN*BB*4];       // [(n*2+b)*4 + h]
__device__ float  g_er[NN*BB*4];
__device__ int    g_deg[NN];           // INVARIANT: zero at entry of each call
__device__ int    g_off[NN + 1];
__device__ int    g_cursor[NN];
__device__ unsigned long long g_tile[NBLK];  // lookback state: zero at entry
__device__ float2 g_edge[EE];          // dst-sorted: (.x = src*8 bits, .y = w)

__device__ __forceinline__ unsigned int h2_bits(__half2 h) {
    return *reinterpret_cast<unsigned int*>(&h);
}
__device__ __forceinline__ __half2 bits_h2(unsigned int u) {
    return *reinterpret_cast<__half2*>(&u);
}

// ---------------------------------------------------------------------------
// K1: feat = x @ W_fc.T + el/er head dots + degree histogram. feat -> fp16.
// 64 rows/block; thread = (rowQuad rq, k4): 4 rows x 4 output cols.
// W LDS loads amortized over 4 rows (33% less LDS traffic than 2-row version).
// ---------------------------------------------------------------------------
__global__ void __launch_bounds__(256) k_featcnt(
        const float* __restrict__ x, const float* __restrict__ Wfc,
        const float* __restrict__ al, const float* __restrict__ ar,
        const int* __restrict__ dst) {
    __shared__ float sWT[64 * 68];
    __shared__ float4 sx4[64][16];
    int tid = threadIdx.x;
    int gid = blockIdx.x * 256 + tid;
    if (gid < EE) atomicAdd(&g_deg[dst[gid]], 1);
    {   int g2 = gid + FC_THREADS;
        if (g2 < EE) atomicAdd(&g_deg[dst[g2]], 1); }

    for (int i = tid; i < 4096; i += 256) {    // coalesced W read, transposed
        int k = i >> 6, j = i & 63;
        sWT[j * 68 + k] = Wfc[i];
    }
    int k4 = tid & 15;
    int rq = tid >> 4;
    int r0 = blockIdx.x * 64 + rq * 4;         // r = b*N + n; NB % 4 == 0
    bool ok = (r0 < NB);
    if (ok) {
        #pragma unroll
        for (int i = 0; i < 4; i++)
            sx4[rq * 4 + i][k4] = ((const float4*)x)[(r0 + i) * 16 + k4];
    }
    __syncthreads();
    if (!ok) return;

    float4 s0 = make_float4(0.f,0.f,0.f,0.f);
    float4 s1 = make_float4(0.f,0.f,0.f,0.f);
    float4 s2 = make_float4(0.f,0.f,0.f,0.f);
    float4 s3 = make_float4(0.f,0.f,0.f,0.f);
    #pragma unroll
    for (int j4 = 0; j4 < 16; j4++) {
        float4 w0 = *(const float4*)&sWT[(4 * j4 + 0) * 68 + 4 * k4];
        float4 w1 = *(const float4*)&sWT[(4 * j4 + 1) * 68 + 4 * k4];
        float4 w2 = *(const float4*)&sWT[(4 * j4 + 2) * 68 + 4 * k4];
        float4 w3 = *(const float4*)&sWT[(4 * j4 + 3) * 68 + 4 * k4];
        float4 xv;
        xv = sx4[rq * 4 + 0][j4];
        s0.x += xv.x*w0.x + xv.y*w1.x + xv.z*w2.x + xv.w*w3.x;
        s0.y += xv.x*w0.y + xv.y*w1.y + xv.z*w2.y + xv.w*w3.y;
        s0.z += xv.x*w0.z + xv.y*w1.z + xv.z*w2.z + xv.w*w3.z;
        s0.w += xv.x*w0.w + xv.y*w1.w + xv.z*w2.w + xv.w*w3.w;
        xv = sx4[rq * 4 + 1][j4];
        s1.x += xv.x*w0.x + xv.y*w1.x + xv.z*w2.x + xv.w*w3.x;
        s1.y += xv.x*w0.y + xv.y*w1.y + xv.z*w2.y + xv.w*w3.y;
        s1.z += xv.x*w0.z + xv.y*w1.z + xv.z*w2.z + xv.w*w3.z;
        s1.w += xv.x*w0.w + xv.y*w1.w + xv.z*w2.w + xv.w*w3.w;
        xv = sx4[rq * 4 + 2][j4];
        s2.x += xv.x*w0.x + xv.y*w1.x + xv.z*w2.x + xv.w*w3.x;
        s2.y += xv.x*w0.y + xv.y*w1.y + xv.z*w2.y + xv.w*w3.y;
        s2.z += xv.x*w0.z + xv.y*w1.z + xv.z*w2.z + xv.w*w3.z;
        s2.w += xv.x*w0.w + xv.y*w1.w + xv.z*w2.w + xv.w*w3.w;
        xv = sx4[rq * 4 + 3][j4];
        s3.x += xv.x*w0.x + xv.y*w1.x + xv.z*w2.x + xv.w*w3.x;
        s3.y += xv.x*w0.y + xv.y*w1.y + xv.z*w2.y + xv.w*w3.y;
        s3.z += xv.x*w0.z + xv.y*w1.z + xv.z*w2.z + xv.w*w3.z;
        s3.w += xv.x*w0.w + xv.y*w1.w + xv.z*w2.w + xv.w*w3.w;
    }

    float4 al4 = __ldg(&((const float4*)al)[k4]);
    float4 ar4 = __ldg(&((const float4*)ar)[k4]);

    #pragma unroll
    for (int i = 0; i < 4; i++) {
        float4 s = (i == 0) ? s0 : (i == 1) ? s1 : (i == 2) ? s2 : s3;
        int r = r0 + i;
        int n = r % NN, b = r / NN;
        int gr = n * 2 + b;
        uint2 u;
        u.x = h2_bits(__float22half2_rn(make_float2(s.x, s.y)));
        u.y = h2_bits(__float22half2_rn(make_float2(s.z, s.w)));
        ((uint2*)&g_feat[gr * 64])[k4] = u;

        float pl = s.x*al4.x + s.y*al4.y + s.z*al4.z + s.w*al4.w;
        float pr = s.x*ar4.x + s.y*ar4.y + s.z*ar4.z + s.w*ar4.w;
        pl += __shfl_down_sync(0xffffffffu, pl, 2);
        pl += __shfl_down_sync(0xffffffffu, pl, 1);
        pr += __shfl_down_sync(0xffffffffu, pr, 2);
        pr += __shfl_down_sync(0xffffffffu, pr, 1);
        if ((k4 & 3) == 0) {
            int h = k4 >> 2;
            g_el[gr * 4 + h] = pl;
            g_er[gr * 4 + h] = pr;
        }
    }
}

// ---------------------------------------------------------------------------
// K2: single-pass exclusive scan (decoupled lookback, 49 tiles all resident)
// ---------------------------------------------------------------------------
__device__ __forceinline__ int warp_incl_scan(int v, int lane) {
    #pragma unroll
    for (int off = 1; off < 32; off <<= 1) {
        int t = __shfl_up_sync(0xffffffffu, v, off);
        if (lane >= off) v += t;
    }
    return v;
}

__global__ void k_scan() {
    __shared__ int wsum[32];
    __shared__ int s_total;
    __shared__ int s_pref;
    int tid = threadIdx.x, lane = tid & 31, wid = tid >> 5;
    int i = blockIdx.x * SCAN_B + tid;
    int v = (i < NN) ? g_deg[i] : 0;
    int incl = warp_incl_scan(v, lane);
    if (lane == 31) wsum[wid] = incl;
    __syncthreads();
    if (wid == 0) {
        int s = wsum[lane];
        int si = warp_incl_scan(s, lane);
        wsum[lane] = si - s;
        if (lane == 31) s_total = si;
    }
    __syncthreads();
    int excl = incl - v + wsum[wid];
    if (tid == 0) {
        int total = s_total;
        int bx = blockIdx.x;
        if (bx == 0) {
            s_pref = 0;
            *(volatile unsigned long long*)&g_tile[0] =
                (2ULL << 62) | (unsigned int)total;
            g_off[NN] = EE;
        } else {
            *(volatile unsigned long long*)&g_tile[bx] =
                (1ULL << 62) | (unsigned int)total;
            int pref = 0;
            int j = bx - 1;
            while (1) {
                unsigned long long t = *(volatile unsigned long long*)&g_tile[j];
                unsigned int st = (unsigned int)(t >> 62);
                if (st == 0) continue;
                pref += (int)(t & 0xffffffffULL);
                if (st == 2) break;
                j--;
            }
            s_pref = pref;
            *(volatile unsigned long long*)&g_tile[bx] =
                (2ULL << 62) | (unsigned int)(pref + total);
        }
    }
    __syncthreads();
    int off = excl + s_pref;
    if (i < NN) { g_off[i] = off; g_cursor[i] = off; }
}

// ---------------------------------------------------------------------------
// K3: scatter edges into dst-sorted order (stores src*8 pre-multiplied);
// resets g_deg / g_tile for the NEXT call.
// ---------------------------------------------------------------------------
__global__ void k_scatter(const int* __restrict__ src, const int* __restrict__ dst,
                          const float* __restrict__ w) {
    int e = blockIdx.x * blockDim.x + threadIdx.x;
    if (e >= EE) return;
    if (e < NN) g_deg[e] = 0;
    if (e < NBLK) g_tile[e] = 0ULL;
    int t = dst[e];
    int pos = atomicAdd(&g_cursor[t], 1);
    g_edge[pos] = make_float2(__int_as_float(src[e] * 8), w[e]);
}

// ---------------------------------------------------------------------------
// K4: one warp per node. Lane owns 4 elems (one (b,h)); feat gather is one
// 8B fp16 load per lane per edge. No max tracking. Unroll x2.
// Edge record carries s*8: el idx = s8+q, feat half-offset = s8*16.
// ---------------------------------------------------------------------------
__device__ __forceinline__ float lk(float v) { return (v > 0.f) ? v : 0.1f * v; }

__device__ __forceinline__ void feat4(int s8, int lane, float2& f01, float2& f23) {
    uint2 u = __ldg((const uint2*)(g_feat + s8 * 16 + 4 * lane));
    f01 = __half22float2(bits_h2(u.x));
    f23 = __half22float2(bits_h2(u.y));
}

__global__ void __launch_bounds__(256, 6) k_agg_out(
        const float* __restrict__ Wout, const float* __restrict__ bout,
        float* __restrict__ out) {
    __shared__ float sAcc[8][128];
    int tid = threadIdx.x;
    int warp = tid >> 5;
    int lane = tid & 31;
    int n = blockIdx.x * 8 + warp;           // grid*8 == NN exactly

    int q = lane >> 2;                  // (b*4 + h) for this lane
    float er_l = g_er[n * 8 + q];

    int beg = g_off[n], end = g_off[n + 1];

    float4 a = make_float4(0.f, 0.f, 0.f, 0.f);
    float  d = 0.f;

    int e = beg;
    if ((e & 1) && e < end) {            // head peel -> e even (16B alignment)
        float2 ed = __ldg(&g_edge[e]);
        int   s8 = __float_as_int(ed.x);
        float xs = __expf(lk(__ldg(&g_el[s8 + q]) + er_l) * ed.y);
        float2 f01, f23; feat4(s8, lane, f01, f23);
        d += xs;
        a.x += xs * f01.x; a.y += xs * f01.y; a.z += xs * f23.x; a.w += xs * f23.y;
        e++;
    }
    for (; e + 1 < end; e += 2) {        // e even: aligned float4 edge load
        float4 eAB = __ldg((const float4*)&g_edge[e]);
        int s8A = __float_as_int(eAB.x), s8B = __float_as_int(eAB.z);

        float elA = __ldg(&g_el[s8A + q]);
        float elB = __ldg(&g_el[s8B + q]);
        float2 fA01, fA23; feat4(s8A, lane, fA01, fA23);
        float2 fB01, fB23; feat4(s8B, lane, fB01, fB23);

        float xA = __expf(lk(elA + er_l) * eAB.y);
        float xB = __expf(lk(elB + er_l) * eAB.w);
        d += xA + xB;
        a.x += xA * fA01.x + xB * fB01.x;
        a.y += xA * fA01.y + xB * fB01.y;
        a.z += xA * fA23.x + xB * fB23.x;
        a.w += xA * fA23.y + xB * fB23.y;
    }
    if (e < end) {                       // tail edge
        float2 ed = __ldg(&g_edge[e]);
        int   s8 = __float_as_int(ed.x);
        float xs = __expf(lk(__ldg(&g_el[s8 + q]) + er_l) * ed.y);
        float2 f01, f23; feat4(s8, lane, f01, f23);
        d += xs;
        a.x += xs * f01.x; a.y += xs * f01.y; a.z += xs * f23.x; a.w += xs * f23.y;
    }

    float inv = (d > 0.f) ? 1.f / d : 0.f;
    *(float4*)&sAcc[warp][4 * lane] =
        make_float4(a.x * inv, a.y * inv, a.z * inv, a.w * inv);
    __syncwarp();

    // two-pass epilogue: registers for W rows reused between passes
    #pragma unroll
    for (int pass = 0; pass < 2; pass++) {
        int o = lane + pass * 32;
        float4 wR[4];
        #pragma unroll
        for (int qq = 0; qq < 4; qq++)
            wR[qq] = __ldg(&((const float4*)&Wout[o * 16])[qq]);
        float bias = __ldg(&bout[o]);

        #pragma unroll
        for (int b = 0; b < 2; b++) {
            #pragma unroll
            for (int h = 0; h < 4; h++) {
                const float4* ap = (const float4*)&sAcc[warp][b * 64 + h * 16];
                float acc = bias;
                #pragma unroll
                for (int qq = 0; qq < 4; qq++) {
                    float4 av = ap[qq];
                    acc += av.x * wR[qq].x + av.y * wR[qq].y
                         + av.z * wR[qq].z + av.w * wR[qq].w;
                }
                out[((b * NN + n) * 4 + h) * 64 + o] = acc;
            }
        }
    }
}

// ---------------------------------------------------------------------------
// inputs: vt, x, w, src, dst, W_fc, attn_l, attn_r, W_out, b_out
// ---------------------------------------------------------------------------
extern "C" void kernel_launch(void* const* d_in, const int* in_sizes, int n_in,
                              void* d_out, int out_size) {
    const float* x    = (const float*)d_in[1];
    const float* w    = (const float*)d_in[2];
    const int*   src  = (const int*)  d_in[3];
    const int*   dst  = (const int*)  d_in[4];
    const float* Wfc  = (const float*)d_in[5];
    const float* al   = (const float*)d_in[6];
    const float* ar   = (const float*)d_in[7];
    const float* Wout = (const float*)d_in[8];
    const float* bout = (const float*)d_in[9];
    float* out = (float*)d_out;

    k_featcnt<<<FC_BLOCKS, 256>>>(x, Wfc, al, ar, dst);   // 1563 blocks
    k_scan<<<NBLK, SCAN_B>>>();
    k_scatter<<<(EE + 255) / 256, 256>>>(src, dst, w);
    k_agg_out<<<NN / 8, 256>>>(Wout, bout, out);
}